// round 15
// baseline (speedup 1.0000x reference)
#include <cuda_runtime.h>
#include <cstdint>

// DiscreteAutoregressiveFlow: exact one-hot algebra over Z_257.
// next = (x_t * m[p] + c[p]) mod 257, per-state (m,c) from argmax of W[p]+b.
// Round 15: k_A = tables + extract (PURE READ stream). k_BC = 512 chain
// blocks (dispatched first, uint2/LDS.64 table) + 4096 zero-fill blocks
// (smem-free, co-resident, soak the idle DRAM pipe under chain ALU).
// Last chain block per batch: smem stitch + replay + scatter after zeros.

#define V        257
#define B        64
#define L        1024
#define SEGLEN   16
#define UNITS    8                        // segments per chain block
#define BPB      8                        // chain blocks per batch
#define CHAIN    (B * BPB)                // 512 chain blocks
#define ZPBAT    64                       // zero blocks per batch
#define ZBLK     (B * ZPBAT)              // 4096 zero blocks
#define ZU4      1028                     // uint4 per zero block (65792/64)
#define REP      8                        // table replication factor
#define NST      258                      // states 0..256 plus 257 = ZERO
#define NSLOT    514                      // doubled-table slots
#define TOTAL4   ((B * L * V) / 4)        // 4,214,784 uint4
#define U4PB     ((L * V) / 4)            // 65792 uint4 per batch
#define TBLK     33                       // table blocks (264 warps >= 258)
#define XBLK     (TOTAL4 / 2048)          // 2058 extract blocks

// Slot convention: slot 0 = state 257 (ZERO/dead); slot s in [1,513] = state
// (s-1) mod 257. Step: z = x*m + c (alive z <= 65792); z mod 257 ==
// (z&255)-(z>>8) (mod 257); sl = lo-hi+258 in [1,513] alive, 0 for the dead
// trap (m=0, c=66048 -> hi=258). Branch-free.

__device__ __align__(16) uint2 g_tabRD[NSLOT * REP];     // doubled+replicated {m,c}
__device__ __align__(16) int   g_xidx[B * L];
__device__ __align__(16) short g_bmap[CHAIN * NST];      // composed block maps
__device__ __align__(16) short g_seg[CHAIN * UNITS * NST]; // per-unit maps
__device__ int g_done[B];                                // zero-init; self-reset
__device__ int g_zrdy[B];                                // zero-init; self-reset

// ---------------------------------------------------------------------------
// K_A: tables (33 blocks) + extract (pure read stream, 2058 blocks).
// ---------------------------------------------------------------------------
__global__ void __launch_bounds__(256) k_A(const float* __restrict__ W,
                                           const float* __restrict__ bb,
                                           const int*   __restrict__ inv_table,
                                           const uint4* __restrict__ x) {
    int bid = blockIdx.x;
    int tid = threadIdx.x;

    if (bid < TBLK) {
        int p    = bid * 8 + (tid >> 5);
        int lane = tid & 31;
        if (p >= NST) return;
        const float* wrow = (p < V) ? (W + (size_t)p * (2 * V)) : nullptr;
        int bestj[2];
        #pragma unroll
        for (int h = 0; h < 2; h++) {
            float bv = -3.402823466e38f;
            int   bj = 0;
            for (int j = lane; j < V; j += 32) {
                int   col = h * V + j;
                float v   = bb[col] + (wrow ? wrow[col] : 0.0f);
                if (v > bv) { bv = v; bj = j; }     // first-max == jnp.argmax
            }
            #pragma unroll
            for (int off = 16; off; off >>= 1) {
                float ov = __shfl_down_sync(0xffffffffu, bv, off);
                int   oj = __shfl_down_sync(0xffffffffu, bj, off);
                if (ov > bv || (ov == bv && oj < bj)) { bv = ov; bj = oj; }
            }
            bestj[h] = bj;
        }
        unsigned mv = 0, cv = 0;
        if (lane == 0) {
            int l = bestj[0], s = bestj[1];
            int m = inv_table[s];                 // 0 iff s==0
            if (m != 0) { mv = (unsigned)m; cv = (unsigned)((V - (l * m) % V) % V); }
            else        { mv = 0u;          cv = 66048u; }   // dead trap -> slot 0
        }
        mv = __shfl_sync(0xffffffffu, mv, 0);
        cv = __shfl_sync(0xffffffffu, cv, 0);
        // replicate into the doubled table: state p -> slots
        //   p<=255: p+1 and p+258;  p==256: 257 only;  p==257 (ZERO): 0 only.
        int slotA = (p == V) ? 0 : p + 1;
        if (lane < REP)
            g_tabRD[slotA * REP + lane] = make_uint2(mv, cv);
        else if (lane < 2 * REP && p < 256)
            g_tabRD[(p + 258) * REP + (lane - REP)] = make_uint2(mv, cv);
        return;
    }

    // extract: 8 coalesced uint4 loads front-batched (MLP_p1 = 8)
    int base = (bid - TBLK) * 2048 + tid;
    uint4 v[8];
    #pragma unroll
    for (int k = 0; k < 8; k++) v[k] = x[base + k * 256];
    #pragma unroll
    for (int k = 0; k < 8; k++) {
        if (v[k].x | v[k].y | v[k].z | v[k].w) {
            unsigned a[4] = { v[k].x, v[k].y, v[k].z, v[k].w };
            int eb = (base + k * 256) * 4;
            #pragma unroll
            for (int j = 0; j < 4; j++) {
                if (a[j] != 0u) {
                    int idx = eb + j;
                    int row = idx / V;
                    g_xidx[row] = idx - row * V;
                }
            }
        }
    }
}

// ---------------------------------------------------------------------------
// K_BC: [512 chain blocks][4096 zero blocks]. Chains own the SMs (42KB smem,
// one wave); zeros co-reside (smem-free) and stream 67MB of stores under the
// chain ALU. Last chain block per batch: smem stitch + replay + scatter
// (after its batch's zeros complete).
// ---------------------------------------------------------------------------
__global__ void __launch_bounds__(256) k_BC(float* __restrict__ out) {
    __shared__ __align__(16) uint2 tabR[NSLOT * REP];    // 32896 B
    __shared__ __align__(16) short segmapS[UNITS * NST]; // 4128 B (reused as bmaps)
    __shared__ __align__(16) int   sx[L];                // 4096 B
    __shared__ __align__(16) int   sxs[SEGLEN * UNITS];  // [t*8 + u]
    __shared__ short entryS[UNITS * BPB];                // 64 segment entries
    __shared__ short blkentS[BPB];
    __shared__ int   isLast;

    int bid = blockIdx.x;
    int tid = threadIdx.x;

    // ---------------- role: zero-fill (write stream) ----------------
    if (bid >= CHAIN) {
        int zb = bid - CHAIN;                            // 0..4095
        int b  = zb >> 6, j = zb & 63;
        int base = b * U4PB + j * ZU4;                   // 1028 uint4
        uint4* o4 = (uint4*)out;
        uint4 z = make_uint4(0u, 0u, 0u, 0u);
        #pragma unroll
        for (int k = 0; k < 4; k++) o4[base + tid + k * 256] = z;
        if (tid < ZU4 - 1024) o4[base + 1024 + tid] = z;
        __threadfence();
        __syncthreads();
        if (tid == 0) atomicAdd(&g_zrdy[b], 1);
        return;
    }

    // ---------------- role: chain block ----------------
    int b   = bid / BPB;
    int blk = bid % BPB;

    // fill: 2056 uint4, fully coalesced (tabRD written by k_A)
    {
        const uint4* src = (const uint4*)g_tabRD;
        uint4* dst = (uint4*)tabR;
        #pragma unroll
        for (int k = 0; k < 8; k++) dst[tid + k * 256] = src[tid + k * 256];
        if (tid < (NSLOT * REP * 8) / 16 - 2048) dst[2048 + tid] = src[2048 + tid];
    }
    if (tid < UNITS * SEGLEN) {
        int u = tid >> 4, t = tid & 15;
        sxs[t * 8 + u] = g_xidx[b * L + (blk * UNITS + u) * SEGLEN + t];
    }
    __syncthreads();

    // ---- segment maps: 8 branch-free chains/thread + extra on t<16 ----
    int rep = tid & (REP - 1);
    int xst = 256 + (tid & 1);          // extra-chain state (threads 0..15)
    int xun = (tid >> 1) & 7;           // extra-chain unit
    bool extra = (tid < 16);

    int slot[9];
    #pragma unroll
    for (int j = 0; j < 8; j++) slot[j] = tid + 1;       // state tid -> slot tid+1
    slot[8] = (xst == V) ? 0 : xst + 1;

    #pragma unroll
    for (int t = 0; t < SEGLEN; t++) {
        uint4 xv0 = *(const uint4*)&sxs[t * 8];
        uint4 xv1 = *(const uint4*)&sxs[t * 8 + 4];
        unsigned xs[8] = { xv0.x, xv0.y, xv0.z, xv0.w,
                           xv1.x, xv1.y, xv1.z, xv1.w };
        #pragma unroll
        for (int j = 0; j < 8; j++) {
            uint2 e = tabR[slot[j] * REP + rep];         // LDS.64: {m, c}
            unsigned z = xs[j] * e.x + e.y;
            slot[j] = (int)(z & 255u) - (int)(z >> 8) + 258;
        }
        if (extra) {
            uint2 e = tabR[slot[8] * REP + rep];
            unsigned z = (unsigned)sxs[t * 8 + xun] * e.x + e.y;
            slot[8] = (int)(z & 255u) - (int)(z >> 8) + 258;
        }
    }

    #pragma unroll
    for (int j = 0; j < 8; j++) {
        int s = slot[j];
        segmapS[j * NST + tid] =
            (short)((s == 0) ? V : ((s <= V) ? s - 1 : s - (V + 1)));
    }
    if (extra) {
        int s = slot[8];
        segmapS[xun * NST + xst] =
            (short)((s == 0) ? V : ((s <= V) ? s - 1 : s - (V + 1)));
    }
    __syncthreads();

    // ---- publish per-unit maps + composed block map ----
    {
        const uint4* src = (const uint4*)segmapS;        // 258 uint4
        uint4* dst = (uint4*)(g_seg + (size_t)bid * UNITS * NST);
        dst[tid] = src[tid];
        if (tid < 2) dst[256 + tid] = src[256 + tid];
    }
    for (int p = tid; p < NST; p += 256) {
        int cur = segmapS[p];
        #pragma unroll
        for (int u = 1; u < UNITS; u++) cur = segmapS[u * NST + cur];
        g_bmap[(size_t)bid * NST + p] = (short)cur;
    }
    __threadfence();
    __syncthreads();
    if (tid == 0) isLast = (atomicAdd(&g_done[b], 1) == BPB - 1);
    __syncthreads();
    if (!isLast) return;
    __threadfence();                                     // acquire peers' maps

    // ---- stitch: stage 8 block-maps into smem (reuse segmapS), walk in LDS
    ((uint4*)sx)[tid] = ((const uint4*)(g_xidx + b * L))[tid];  // batch x
    {
        const uint4* src = (const uint4*)(g_bmap + (size_t)(b * BPB) * NST);
        uint4* dst = (uint4*)segmapS;                    // 258 uint4 (4128 B)
        dst[tid] = src[tid];
        if (tid < 2) dst[256 + tid] = src[256 + tid];
    }
    __syncthreads();
    if (tid == 0) {
        int st = V;                                      // ZERO
        #pragma unroll
        for (int k = 0; k < BPB; k++) {
            blkentS[k] = (short)st;
            st = segmapS[k * NST + st];                  // LDS chain
        }
    }
    __syncthreads();
    if (tid < BPB) {
        int k = tid;
        int e = blkentS[k];
        const short* seg = g_seg + (size_t)(b * BPB + k) * UNITS * NST;
        #pragma unroll
        for (int u = 0; u < UNITS; u++) {
            entryS[k * UNITS + u] = (short)e;
            e = seg[u * NST + e];                        // 8 serial L2 (parallel in k)
        }
    }
    // wait for this batch's zeros (done long ago: zeros stream ~11us < chains)
    if (tid == 0) {
        while (*(volatile int*)&g_zrdy[b] < ZPBAT) __nanosleep(32);
    }
    __syncthreads();
    __threadfence();

    // ---- replay + scatter: 64 threads, one 16-step chain each ----
    if (tid < BPB * UNITS) {
        int seg = tid;
        int ent = entryS[seg];
        int sl  = (ent == V) ? 0 : ent + 1;
        float* orow = out + (size_t)(b * L + seg * SEGLEN) * V;
        #pragma unroll
        for (int t = 0; t < SEGLEN; t++) {
            uint2 e = tabR[sl * REP + (tid & (REP - 1))];
            unsigned z = (unsigned)sx[seg * SEGLEN + t] * e.x + e.y;
            sl = (int)(z & 255u) - (int)(z >> 8) + 258;
            if (sl != 0) {
                int oi = (sl <= V) ? sl - 1 : sl - (V + 1);
                orow[(size_t)t * V + oi] = 1.0f;
            }
        }
    }
    __syncthreads();
    if (tid == 0) {                                      // self-reset for replay
        g_done[b] = 0;
        g_zrdy[b] = 0;
    }
}

// ---------------------------------------------------------------------------
extern "C" void kernel_launch(void* const* d_in, const int* in_sizes, int n_in,
                              void* d_out, int out_size) {
    const float* x   = (const float*)d_in[0];   // [B, L, V] f32
    const float* W   = (const float*)d_in[1];   // [V, 2V]   f32
    const float* bb  = (const float*)d_in[2];   // [2V]      f32
    const int*   inv = (const int*)  d_in[3];   // [V]       i32

    k_A<<<TBLK + XBLK, 256>>>(W, bb, inv, (const uint4*)x);
    k_BC<<<CHAIN + ZBLK, 256>>>((float*)d_out);
}